// round 1
// baseline (speedup 1.0000x reference)
#include <cuda_runtime.h>
#include <math.h>

#define BB   4
#define LLEN 1024
#define DD   768
#define HH   12
#define NE_  42
#define MM   4
#define PP   512
#define NL_  97
#define NG_  12      // D / BLK
#define TPB  16      // pairs per bilinear block
#define SP   20      // padded pair pitch in shared (float4-aligned)

// ---------------- scratch (static device globals; no runtime allocation) ----
__device__ float g_ent_emb[BB*NE_*DD];                 // [B,NE,D]
__device__ float g_ent_att[BB*NE_*HH*LLEN];            // [B,NE,H,L]
__device__ float g_wnorm[BB*PP*LLEN];                  // [B,P,L]
__device__ float g_rs[BB*PP*DD];                       // [B,P,D]
__device__ float g_hsW[BB*NE_*DD];                     // E @ W_head[:D]
__device__ float g_tsW[BB*NE_*DD];                     // E @ W_tail[:D]
__device__ float g_zs[BB*PP*DD];
__device__ float g_zo[BB*PP*DD];
__device__ float g_part[2][BB*PP*NL_];                 // bilinear partials (2 g-halves)

// ---------------- kernel 1: entity embeddings (logsumexp over M mentions) ---
__global__ void k_ent_emb(const float* __restrict__ seq, const int* __restrict__ mpos){
    int be = blockIdx.x;            // b*NE + e
    int b  = be / NE_;
    const int* mp = mpos + be*MM;
    int p0 = mp[0]+1, p1 = mp[1]+1, p2 = mp[2]+1, p3 = mp[3]+1;
    const float* s = seq + (size_t)b*LLEN*DD;
    for (int d = threadIdx.x; d < DD; d += blockDim.x){
        float v0 = s[(size_t)p0*DD+d], v1 = s[(size_t)p1*DD+d];
        float v2 = s[(size_t)p2*DD+d], v3 = s[(size_t)p3*DD+d];
        float mx = fmaxf(fmaxf(v0,v1), fmaxf(v2,v3));
        float sm = expf(v0-mx)+expf(v1-mx)+expf(v2-mx)+expf(v3-mx);
        g_ent_emb[(size_t)be*DD + d] = mx + logf(sm);
    }
}

// ---------------- kernel 2: entity attention rows (mean over M mentions) ----
__global__ void k_ent_att(const float* __restrict__ att, const int* __restrict__ mpos){
    int beh = blockIdx.x;           // (b*NE+e)*H + h
    int h   = beh % HH;
    int be  = beh / HH;
    int b   = be / NE_;
    const int* mp = mpos + be*MM;
    int p0 = mp[0]+1, p1 = mp[1]+1, p2 = mp[2]+1, p3 = mp[3]+1;
    const float* A = att + ((size_t)(b*HH + h))*LLEN*LLEN;
    float* out = g_ent_att + ((size_t)be*HH + h)*LLEN;
    for (int l = threadIdx.x; l < LLEN; l += blockDim.x){
        float v = A[(size_t)p0*LLEN+l] + A[(size_t)p1*LLEN+l]
                + A[(size_t)p2*LLEN+l] + A[(size_t)p3*LLEN+l];
        out[l] = v * 0.25f;
    }
}

// ---------------- kernel 3: per-pair normalized context weights -------------
__global__ void k_pairw(const int* __restrict__ hts){
    int bp = blockIdx.x;            // b*P + p
    int b  = bp >> 9;               // /PP
    int hi = hts[bp*2+0], ti = hts[bp*2+1];
    __shared__ float sd[LLEN];
    __shared__ float red[8];
    const float* Ah = g_ent_att + ((size_t)(b*NE_ + hi))*HH*LLEN;
    const float* At = g_ent_att + ((size_t)(b*NE_ + ti))*HH*LLEN;
    float lsum = 0.f;
    for (int l = threadIdx.x; l < LLEN; l += blockDim.x){
        float s = 0.f;
        #pragma unroll
        for (int h = 0; h < HH; ++h) s += Ah[h*LLEN+l]*At[h*LLEN+l];
        sd[l] = s; lsum += s;
    }
    #pragma unroll
    for (int o = 16; o; o >>= 1) lsum += __shfl_xor_sync(0xFFFFFFFFu, lsum, o);
    if ((threadIdx.x & 31) == 0) red[threadIdx.x >> 5] = lsum;
    __syncthreads();
    float total = red[0]+red[1]+red[2]+red[3]+red[4]+red[5]+red[6]+red[7];
    float inv = 1.f / (total + (float)HH*1e-5f);   // folds the /H + 1e-5 normalization
    float* wout = g_wnorm + (size_t)bp*LLEN;
    for (int l = threadIdx.x; l < LLEN; l += blockDim.x) wout[l] = sd[l]*inv;
}

// ---------------- generic fp32 GEMM: C = A@W (+gathered eW + bias, tanh) ----
__global__ void __launch_bounds__(256) k_gemm(
    const float* __restrict__ Ag, int lda, long sA,
    const float* __restrict__ Wg, int ldw, long sW,
    float* __restrict__ Cg, int ldc, long sC,
    int Mr, int K,
    const float* __restrict__ bias,
    const float* __restrict__ eW,
    const int* __restrict__ hts, int which)
{
    const float* A = Ag + (size_t)sA*blockIdx.z;
    const float* W = Wg + (size_t)sW*blockIdx.z;
    float*       C = Cg + (size_t)sC*blockIdx.z;
    __shared__ float As[64][17];
    __shared__ float Ws[16][64];
    int tx = threadIdx.x & 15, ty = threadIdx.x >> 4;
    int row0 = blockIdx.y*64, col0 = blockIdx.x*64;
    float acc[4][4] = {};
    for (int kt = 0; kt < K; kt += 16){
        for (int idx = threadIdx.x; idx < 64*16; idx += 256){
            int r = idx >> 4, c = idx & 15;
            int rr = row0 + r;
            As[r][c] = (rr < Mr) ? A[(size_t)rr*lda + kt + c] : 0.f;
        }
        for (int idx = threadIdx.x; idx < 16*64; idx += 256){
            int r = idx >> 6, c = idx & 63;
            Ws[r][c] = W[(size_t)(kt+r)*ldw + col0 + c];
        }
        __syncthreads();
        #pragma unroll
        for (int kk = 0; kk < 16; ++kk){
            float a0 = As[ty*4+0][kk], a1 = As[ty*4+1][kk];
            float a2 = As[ty*4+2][kk], a3 = As[ty*4+3][kk];
            float4 w = reinterpret_cast<const float4*>(&Ws[kk][0])[tx];
            acc[0][0] += a0*w.x; acc[0][1] += a0*w.y; acc[0][2] += a0*w.z; acc[0][3] += a0*w.w;
            acc[1][0] += a1*w.x; acc[1][1] += a1*w.y; acc[1][2] += a1*w.z; acc[1][3] += a1*w.w;
            acc[2][0] += a2*w.x; acc[2][1] += a2*w.y; acc[2][2] += a2*w.z; acc[2][3] += a2*w.w;
            acc[3][0] += a3*w.x; acc[3][1] += a3*w.y; acc[3][2] += a3*w.z; acc[3][3] += a3*w.w;
        }
        __syncthreads();
    }
    #pragma unroll
    for (int i = 0; i < 4; ++i){
        int row = row0 + ty*4 + i;
        if (row >= Mr) continue;
        const float* ev = 0;
        if (eW){
            int bb = row / PP;
            int eidx = hts[row*2 + which];
            ev = eW + ((size_t)(bb*NE_ + eidx))*DD;
        }
        #pragma unroll
        for (int j = 0; j < 4; ++j){
            int col = col0 + tx*4 + j;
            float v = acc[i][j];
            if (ev) v = tanhf(v + ev[col] + bias[col]);
            C[(size_t)row*ldc + col] = v;
        }
    }
}

// ---------------- grouped bilinear: logits partials per g-half --------------
// A[p, (g,i,j)] = zs[p,g*64+i]*zo[p,g*64+j], C = A @ W_bi[49152,97]
__global__ void __launch_bounds__(128) k_bilinear(const float* __restrict__ Wbi){
    int b    = blockIdx.y;
    int p0   = blockIdx.x * TPB;
    int half = blockIdx.z;
    int g0   = half * (NG_/2);
    int tid  = threadIdx.x;
    int nthr = tid & 31;
    int pgq  = tid >> 5;            // 0..3 -> pairs pgq*4 .. pgq*4+3

    __shared__ float  zs_sh[64*SP];       // [c][p], pitch SP
    __shared__ float  zo_sh[64*SP];
    __shared__ float4 a_sh4[64*(SP/4)];   // [j][p/4]
    __shared__ float  Wsh[64*128];        // [j][n], pitch 128 (n>=97 garbage, discarded)
    float* a_shf = reinterpret_cast<float*>(a_sh4);

    float acc[4][4];
    #pragma unroll
    for (int i = 0; i < 4; ++i)
        #pragma unroll
        for (int q = 0; q < 4; ++q) acc[i][q] = 0.f;

    const float* zs = g_zs + ((size_t)(b*PP + p0))*DD;
    const float* zo = g_zo + ((size_t)(b*PP + p0))*DD;

    for (int g = g0; g < g0 + NG_/2; ++g){
        for (int idx = tid; idx < TPB*64; idx += 128){
            int p = idx >> 6, c = idx & 63;
            float vs = zs[(size_t)p*DD + g*64 + c];
            float vo = zo[(size_t)p*DD + g*64 + c];
            zs_sh[c*SP + p] = vs;
            zo_sh[c*SP + p] = vo;
        }
        __syncthreads();
        for (int i = 0; i < 64; ++i){
            const float* Wrow = Wbi + ((size_t)(g*64 + i))*64*NL_;
            for (int idx = tid; idx < 64*NL_; idx += 128){
                int j = idx / NL_; int n = idx - j*NL_;
                Wsh[j*128 + n] = Wrow[(size_t)j*NL_ + n];
            }
            for (int idx = tid; idx < 64*TPB; idx += 128){
                int j = idx >> 4, p = idx & 15;
                a_shf[j*SP + p] = zs_sh[i*SP + p] * zo_sh[j*SP + p];
            }
            __syncthreads();
            #pragma unroll 4
            for (int j = 0; j < 64; ++j){
                float4 a = a_sh4[j*(SP/4) + pgq];         // broadcast LDS.128
                float w0 = Wsh[j*128 + nthr];
                float w1 = Wsh[j*128 + nthr + 32];
                float w2 = Wsh[j*128 + nthr + 64];
                float w3 = Wsh[j*128 + nthr + 96];        // garbage unless nthr==0; discarded
                acc[0][0] += a.x*w0; acc[0][1] += a.x*w1; acc[0][2] += a.x*w2; acc[0][3] += a.x*w3;
                acc[1][0] += a.y*w0; acc[1][1] += a.y*w1; acc[1][2] += a.y*w2; acc[1][3] += a.y*w3;
                acc[2][0] += a.z*w0; acc[2][1] += a.z*w1; acc[2][2] += a.z*w2; acc[2][3] += a.z*w3;
                acc[3][0] += a.w*w0; acc[3][1] += a.w*w1; acc[3][2] += a.w*w2; acc[3][3] += a.w*w3;
            }
            __syncthreads();
        }
    }
    #pragma unroll
    for (int pi = 0; pi < 4; ++pi){
        int row = b*PP + p0 + pgq*4 + pi;
        #pragma unroll
        for (int q = 0; q < 4; ++q){
            int n = nthr + 32*q;
            if (n < NL_) g_part[half][(size_t)row*NL_ + n] = acc[pi][q];
        }
    }
}

// ---------------- finish: sum partials + bias -------------------------------
__global__ void k_finish(float* __restrict__ out, const float* __restrict__ b_bi){
    int i = blockIdx.x*blockDim.x + threadIdx.x;
    if (i < BB*PP*NL_){
        int n = i % NL_;
        out[i] = g_part[0][i] + g_part[1][i] + b_bi[n];
    }
}

// ---------------- launch ----------------------------------------------------
extern "C" void kernel_launch(void* const* d_in, const int* in_sizes, int n_in,
                              void* d_out, int out_size){
    const float* seq  = (const float*)d_in[0];
    const float* att  = (const float*)d_in[1];
    const int*   mpos = (const int*)  d_in[2];
    const int*   hts  = (const int*)  d_in[3];
    const float* Wh   = (const float*)d_in[4];
    const float* bh   = (const float*)d_in[5];
    const float* Wt   = (const float*)d_in[6];
    const float* bt   = (const float*)d_in[7];
    const float* Wbi  = (const float*)d_in[8];
    const float* bbi  = (const float*)d_in[9];
    float* out = (float*)d_out;

    float *p_ent_emb, *p_wnorm, *p_rs, *p_hsW, *p_tsW, *p_zs, *p_zo;
    cudaGetSymbolAddress((void**)&p_ent_emb, g_ent_emb);
    cudaGetSymbolAddress((void**)&p_wnorm,   g_wnorm);
    cudaGetSymbolAddress((void**)&p_rs,      g_rs);
    cudaGetSymbolAddress((void**)&p_hsW,     g_hsW);
    cudaGetSymbolAddress((void**)&p_tsW,     g_tsW);
    cudaGetSymbolAddress((void**)&p_zs,      g_zs);
    cudaGetSymbolAddress((void**)&p_zo,      g_zo);

    k_ent_emb<<<BB*NE_, 256>>>(seq, mpos);
    k_ent_att<<<BB*NE_*HH, 256>>>(att, mpos);

    // hsW / tsW : [168,768] @ [768,768]
    {
        dim3 grid(DD/64, (BB*NE_ + 63)/64, 1);
        k_gemm<<<grid, 256>>>(p_ent_emb, DD, 0, Wh, DD, 0, p_hsW, DD, 0,
                              BB*NE_, DD, nullptr, nullptr, nullptr, 0);
        k_gemm<<<grid, 256>>>(p_ent_emb, DD, 0, Wt, DD, 0, p_tsW, DD, 0,
                              BB*NE_, DD, nullptr, nullptr, nullptr, 0);
    }

    k_pairw<<<BB*PP, 256>>>(hts);

    // rs : per-doc [512,1024] @ [1024,768]
    {
        dim3 grid(DD/64, PP/64, BB);
        k_gemm<<<grid, 256>>>(p_wnorm, LLEN, (long)PP*LLEN,
                              seq, DD, (long)LLEN*DD,
                              p_rs, DD, (long)PP*DD,
                              PP, LLEN, nullptr, nullptr, nullptr, 0);
    }

    // zs / zo : [2048,768] @ [768,768] + gathered E@W + bias, tanh
    {
        dim3 grid(DD/64, (BB*PP)/64, 1);
        k_gemm<<<grid, 256>>>(p_rs, DD, 0, Wh + (size_t)DD*DD, DD, 0, p_zs, DD, 0,
                              BB*PP, DD, bh, p_hsW, hts, 0);
        k_gemm<<<grid, 256>>>(p_rs, DD, 0, Wt + (size_t)DD*DD, DD, 0, p_zo, DD, 0,
                              BB*PP, DD, bt, p_tsW, hts, 1);
    }

    k_bilinear<<<dim3(PP/TPB, BB, 2), 128>>>(Wbi);
    k_finish<<<(BB*PP*NL_ + 255)/256, 256>>>(out, bbi);
}

// round 2
// speedup vs baseline: 3.4591x; 3.4591x over previous
#include <cuda_runtime.h>
#include <math.h>

#define BB   4
#define LLEN 1024
#define DD   768
#define HH   12
#define NE_  42
#define MM   4
#define PP   512
#define NL_  97
#define NG_  12      // D / BLK
#define TPB2 64      // pairs per bilinear block

// ---------------- scratch (static device globals; no runtime allocation) ----
__device__ float g_ent_emb[BB*NE_*DD];                 // [B,NE,D]
__device__ float g_ent_att[BB*NE_*HH*LLEN];            // [B,NE,H,L]
__device__ float g_wnorm[BB*PP*LLEN];                  // [B,P,L]
__device__ float g_rs[BB*PP*DD];                       // [B,P,D]
__device__ float g_hsW[BB*NE_*DD];                     // E @ W_head[:D]
__device__ float g_tsW[BB*NE_*DD];                     // E @ W_tail[:D]
__device__ float g_zs[BB*PP*DD];
__device__ float g_zo[BB*PP*DD];
__device__ float g_part[4][BB*PP*NL_];                 // bilinear partials (4 g-quarters)

// ---------------- cp.async helpers ------------------------------------------
__device__ __forceinline__ void cpa16(void* dst, const void* src){
    unsigned d = (unsigned)__cvta_generic_to_shared(dst);
    asm volatile("cp.async.cg.shared.global [%0], [%1], 16;\n" :: "r"(d), "l"(src));
}
__device__ __forceinline__ void cpa_commit(){ asm volatile("cp.async.commit_group;\n"); }
__device__ __forceinline__ void cpa_wait1(){ asm volatile("cp.async.wait_group 1;\n"); }
__device__ __forceinline__ void cpa_wait0(){ asm volatile("cp.async.wait_group 0;\n"); }

// ---------------- kernel 1: entity embeddings (logsumexp over M mentions) ---
__global__ void k_ent_emb(const float* __restrict__ seq, const int* __restrict__ mpos){
    int be = blockIdx.x;            // b*NE + e
    int b  = be / NE_;
    const int* mp = mpos + be*MM;
    int p0 = mp[0]+1, p1 = mp[1]+1, p2 = mp[2]+1, p3 = mp[3]+1;
    const float* s = seq + (size_t)b*LLEN*DD;
    for (int d = threadIdx.x; d < DD; d += blockDim.x){
        float v0 = s[(size_t)p0*DD+d], v1 = s[(size_t)p1*DD+d];
        float v2 = s[(size_t)p2*DD+d], v3 = s[(size_t)p3*DD+d];
        float mx = fmaxf(fmaxf(v0,v1), fmaxf(v2,v3));
        float sm = expf(v0-mx)+expf(v1-mx)+expf(v2-mx)+expf(v3-mx);
        g_ent_emb[(size_t)be*DD + d] = mx + logf(sm);
    }
}

// ---------------- kernel 2: entity attention rows (mean over M mentions) ----
__global__ void k_ent_att(const float* __restrict__ att, const int* __restrict__ mpos){
    int beh = blockIdx.x;           // (b*NE+e)*H + h
    int h   = beh % HH;
    int be  = beh / HH;
    int b   = be / NE_;
    const int* mp = mpos + be*MM;
    int p0 = mp[0]+1, p1 = mp[1]+1, p2 = mp[2]+1, p3 = mp[3]+1;
    const float* A = att + ((size_t)(b*HH + h))*LLEN*LLEN;
    float* out = g_ent_att + ((size_t)be*HH + h)*LLEN;
    for (int l = threadIdx.x; l < LLEN; l += blockDim.x){
        float v = A[(size_t)p0*LLEN+l] + A[(size_t)p1*LLEN+l]
                + A[(size_t)p2*LLEN+l] + A[(size_t)p3*LLEN+l];
        out[l] = v * 0.25f;
    }
}

// ---------------- kernel 3: per-pair normalized context weights -------------
__global__ void k_pairw(const int* __restrict__ hts){
    int bp = blockIdx.x;            // b*P + p
    int b  = bp >> 9;               // /PP
    int hi = hts[bp*2+0], ti = hts[bp*2+1];
    __shared__ float sd[LLEN];
    __shared__ float red[8];
    const float* Ah = g_ent_att + ((size_t)(b*NE_ + hi))*HH*LLEN;
    const float* At = g_ent_att + ((size_t)(b*NE_ + ti))*HH*LLEN;
    float lsum = 0.f;
    for (int l = threadIdx.x; l < LLEN; l += blockDim.x){
        float s = 0.f;
        #pragma unroll
        for (int h = 0; h < HH; ++h) s += Ah[h*LLEN+l]*At[h*LLEN+l];
        sd[l] = s; lsum += s;
    }
    #pragma unroll
    for (int o = 16; o; o >>= 1) lsum += __shfl_xor_sync(0xFFFFFFFFu, lsum, o);
    if ((threadIdx.x & 31) == 0) red[threadIdx.x >> 5] = lsum;
    __syncthreads();
    float total = red[0]+red[1]+red[2]+red[3]+red[4]+red[5]+red[6]+red[7];
    float inv = 1.f / (total + (float)HH*1e-5f);   // folds the /H + 1e-5 normalization
    float* wout = g_wnorm + (size_t)bp*LLEN;
    for (int l = threadIdx.x; l < LLEN; l += blockDim.x) wout[l] = sd[l]*inv;
}

// ---------------- fp32 GEMM, cp.async double-buffered -----------------------
// C = A@W; optional epilogue: tanh(C + gathered eW + bias)
__global__ void __launch_bounds__(256) k_gemm(
    const float* __restrict__ Ag, int lda, long sA,
    const float* __restrict__ Wg, int ldw, long sW,
    float* __restrict__ Cg, int ldc, long sC,
    int Mr, int K,
    const float* __restrict__ bias,
    const float* __restrict__ eW,
    const int* __restrict__ hts, int which)
{
    const float* A = Ag + (size_t)sA*blockIdx.z;
    const float* W = Wg + (size_t)sW*blockIdx.z;
    float*       C = Cg + (size_t)sC*blockIdx.z;
    __shared__ __align__(16) float As[2][64][20];
    __shared__ __align__(16) float Ws[2][16][64];
    int tid = threadIdx.x;
    int tx = tid & 15, ty = tid >> 4;
    int row0 = blockIdx.y*64, col0 = blockIdx.x*64;

    int ra = tid >> 2, ca = tid & 3;        // A: 64 rows x 4 float4
    int rw = tid >> 4, cw = tid & 15;       // W: 16 rows x 16 float4
    int rra = min(row0 + ra, Mr-1);         // clamp: garbage rows never stored

    // prologue: stage kt=0
    cpa16(&As[0][ra][ca*4], A + (size_t)rra*lda + ca*4);
    cpa16(&Ws[0][rw][cw*4], W + (size_t)rw*ldw + col0 + cw*4);
    cpa_commit();

    int nk = K >> 4;
    float acc[4][4] = {};
    for (int kt = 0; kt < nk; ++kt){
        if (kt+1 < nk){
            int kb = (kt+1) & 1;
            cpa16(&As[kb][ra][ca*4], A + (size_t)rra*lda + (kt+1)*16 + ca*4);
            cpa16(&Ws[kb][rw][cw*4], W + (size_t)((kt+1)*16 + rw)*ldw + col0 + cw*4);
            cpa_commit();
            cpa_wait1();
        } else {
            cpa_wait0();
        }
        __syncthreads();
        int b = kt & 1;
        #pragma unroll
        for (int kk = 0; kk < 16; ++kk){
            float a0 = As[b][ty*4+0][kk], a1 = As[b][ty*4+1][kk];
            float a2 = As[b][ty*4+2][kk], a3 = As[b][ty*4+3][kk];
            float4 w = *(const float4*)&Ws[b][kk][tx*4];
            acc[0][0] += a0*w.x; acc[0][1] += a0*w.y; acc[0][2] += a0*w.z; acc[0][3] += a0*w.w;
            acc[1][0] += a1*w.x; acc[1][1] += a1*w.y; acc[1][2] += a1*w.z; acc[1][3] += a1*w.w;
            acc[2][0] += a2*w.x; acc[2][1] += a2*w.y; acc[2][2] += a2*w.z; acc[2][3] += a2*w.w;
            acc[3][0] += a3*w.x; acc[3][1] += a3*w.y; acc[3][2] += a3*w.z; acc[3][3] += a3*w.w;
        }
        __syncthreads();
    }
    #pragma unroll
    for (int i = 0; i < 4; ++i){
        int row = row0 + ty*4 + i;
        if (row >= Mr) continue;
        const float* ev = 0;
        if (eW){
            int bb = row / PP;
            int eidx = hts[row*2 + which];
            ev = eW + ((size_t)(bb*NE_ + eidx))*DD;
        }
        #pragma unroll
        for (int j = 0; j < 4; ++j){
            int col = col0 + tx*4 + j;
            float v = acc[i][j];
            if (ev) v = tanhf(v + ev[col] + bias[col]);
            C[(size_t)row*ldc + col] = v;
        }
    }
}

// ---------------- grouped bilinear v2 ---------------------------------------
// 64 pairs/block, 256 threads, 4 g-quarters (3 groups each), W double-buffered.
// warp w: pair-group pg=w&3 (16 pairs), label-half nh=w>>2 (n = nh*64+{0,32}+lane)
#define W_ROW_F4 1552            // 64*97/4
#define W_PAD_F  6272            // 6208 + 64 pad (garbage reads stay in-bounds)
#define SM_ZS    0
#define SM_ZO    (64*65)
#define SM_A     (2*64*65)
#define SM_W     (2*64*65 + 64*64)
#define SMEM_BI  ((2*64*65 + 64*64 + 2*W_PAD_F)*4)

__global__ void __launch_bounds__(256,1) k_bilinear(const float* __restrict__ Wbi){
    extern __shared__ __align__(16) float sm[];
    float* zs_sh = sm + SM_ZS;
    float* zo_sh = sm + SM_ZO;
    float* a_sh  = sm + SM_A;
    float* Wsh   = sm + SM_W;            // [2][W_PAD_F]

    int b  = blockIdx.y;
    int p0 = blockIdx.x * TPB2;
    int qz = blockIdx.z;
    int g0 = qz * 3;
    int tid  = threadIdx.x;
    int lane = tid & 31;
    int w    = tid >> 5;
    int pg   = w & 3;
    int nh   = w >> 2;

    float acc[16][2];
    #pragma unroll
    for (int p = 0; p < 16; ++p){ acc[p][0] = 0.f; acc[p][1] = 0.f; }

    const float* zs = g_zs + ((size_t)(b*PP + p0))*DD;
    const float* zo = g_zo + ((size_t)(b*PP + p0))*DD;
    const float* Wbase = Wbi + (size_t)g0*64*64*NL_;

    // prologue: W row t=0
    {
        const float4* src = (const float4*)Wbase;
        for (int idx = tid; idx < W_ROW_F4; idx += 256)
            cpa16(&Wsh[idx*4], src + idx);
        cpa_commit();
    }

    int sp = tid & 63, jgr = tid >> 6;     // a-staging: p = sp, j = jgr*16+jj

    for (int gg = 0; gg < 3; ++gg){
        int g = g0 + gg;
        // stage zs/zo as [c][p], pitch 65
        for (int idx = tid; idx < 1024; idx += 256){
            int p = idx >> 4, c4 = idx & 15;
            float4 vs = *(const float4*)&zs[(size_t)p*DD + g*64 + c4*4];
            float4 vo = *(const float4*)&zo[(size_t)p*DD + g*64 + c4*4];
            zs_sh[(c4*4+0)*65+p] = vs.x; zs_sh[(c4*4+1)*65+p] = vs.y;
            zs_sh[(c4*4+2)*65+p] = vs.z; zs_sh[(c4*4+3)*65+p] = vs.w;
            zo_sh[(c4*4+0)*65+p] = vo.x; zo_sh[(c4*4+1)*65+p] = vo.y;
            zo_sh[(c4*4+2)*65+p] = vo.z; zo_sh[(c4*4+3)*65+p] = vo.w;
        }
        __syncthreads();
        for (int i = 0; i < 64; ++i){
            int t = gg*64 + i;
            if (t+1 < 192){
                const float4* src = (const float4*)(Wbase + (size_t)(t+1)*64*NL_);
                float* dst = &Wsh[((t+1)&1)*W_PAD_F];
                for (int idx = tid; idx < W_ROW_F4; idx += 256)
                    cpa16(dst + idx*4, src + idx);
                cpa_commit();
                cpa_wait1();
            } else {
                cpa_wait0();
            }
            // stage a[j][p] = zs[i][p]*zo[j][p]
            {
                float si = zs_sh[i*65 + sp];
                #pragma unroll
                for (int jj = 0; jj < 16; ++jj){
                    int j = jgr*16 + jj;
                    a_sh[j*64 + sp] = si * zo_sh[j*65 + sp];
                }
            }
            __syncthreads();
            const float* Wrow = &Wsh[(t&1)*W_PAD_F];
            const float* wp   = Wrow + nh*64 + lane;
            const float* ap   = a_sh + pg*16;
            #pragma unroll 4
            for (int j = 0; j < 64; ++j){
                float4 a0 = *(const float4*)(ap);      // broadcast LDS.128
                float4 a1 = *(const float4*)(ap + 4);
                float4 a2 = *(const float4*)(ap + 8);
                float4 a3 = *(const float4*)(ap + 12);
                float w0 = wp[0];
                float w1 = wp[32];                     // may read pad for n>=97; discarded
                acc[ 0][0]+=a0.x*w0; acc[ 0][1]+=a0.x*w1;
                acc[ 1][0]+=a0.y*w0; acc[ 1][1]+=a0.y*w1;
                acc[ 2][0]+=a0.z*w0; acc[ 2][1]+=a0.z*w1;
                acc[ 3][0]+=a0.w*w0; acc[ 3][1]+=a0.w*w1;
                acc[ 4][0]+=a1.x*w0; acc[ 4][1]+=a1.x*w1;
                acc[ 5][0]+=a1.y*w0; acc[ 5][1]+=a1.y*w1;
                acc[ 6][0]+=a1.z*w0; acc[ 6][1]+=a1.z*w1;
                acc[ 7][0]+=a1.w*w0; acc[ 7][1]+=a1.w*w1;
                acc[ 8][0]+=a2.x*w0; acc[ 8][1]+=a2.x*w1;
                acc[ 9][0]+=a2.y*w0; acc[ 9][1]+=a2.y*w1;
                acc[10][0]+=a2.z*w0; acc[10][1]+=a2.z*w1;
                acc[11][0]+=a2.w*w0; acc[11][1]+=a2.w*w1;
                acc[12][0]+=a3.x*w0; acc[12][1]+=a3.x*w1;
                acc[13][0]+=a3.y*w0; acc[13][1]+=a3.y*w1;
                acc[14][0]+=a3.z*w0; acc[14][1]+=a3.z*w1;
                acc[15][0]+=a3.w*w0; acc[15][1]+=a3.w*w1;
                ap += 64; wp += NL_;
            }
            __syncthreads();
        }
    }
    // store quarter partials
    #pragma unroll
    for (int p = 0; p < 16; ++p){
        int row = b*PP + p0 + pg*16 + p;
        #pragma unroll
        for (int q = 0; q < 2; ++q){
            int n = nh*64 + q*32 + lane;
            if (n < NL_) g_part[qz][(size_t)row*NL_ + n] = acc[p][q];
        }
    }
}

// ---------------- finish: sum partials + bias -------------------------------
__global__ void k_finish(float* __restrict__ out, const float* __restrict__ b_bi){
    int i = blockIdx.x*blockDim.x + threadIdx.x;
    if (i < BB*PP*NL_){
        int n = i % NL_;
        out[i] = g_part[0][i] + g_part[1][i] + g_part[2][i] + g_part[3][i] + b_bi[n];
    }
}

// ---------------- launch ----------------------------------------------------
extern "C" void kernel_launch(void* const* d_in, const int* in_sizes, int n_in,
                              void* d_out, int out_size){
    const float* seq  = (const float*)d_in[0];
    const float* att  = (const float*)d_in[1];
    const int*   mpos = (const int*)  d_in[2];
    const int*   hts  = (const int*)  d_in[3];
    const float* Wh   = (const float*)d_in[4];
    const float* bh   = (const float*)d_in[5];
    const float* Wt   = (const float*)d_in[6];
    const float* bt   = (const float*)d_in[7];
    const float* Wbi  = (const float*)d_in[8];
    const float* bbi  = (const float*)d_in[9];
    float* out = (float*)d_out;

    float *p_ent_emb, *p_wnorm, *p_rs, *p_hsW, *p_tsW, *p_zs, *p_zo;
    cudaGetSymbolAddress((void**)&p_ent_emb, g_ent_emb);
    cudaGetSymbolAddress((void**)&p_wnorm,   g_wnorm);
    cudaGetSymbolAddress((void**)&p_rs,      g_rs);
    cudaGetSymbolAddress((void**)&p_hsW,     g_hsW);
    cudaGetSymbolAddress((void**)&p_tsW,     g_tsW);
    cudaGetSymbolAddress((void**)&p_zs,      g_zs);
    cudaGetSymbolAddress((void**)&p_zo,      g_zo);

    static bool attr_done = false;
    if (!attr_done){
        cudaFuncSetAttribute(k_bilinear, cudaFuncAttributeMaxDynamicSharedMemorySize, SMEM_BI);
        attr_done = true;
    }

    k_ent_emb<<<BB*NE_, 256>>>(seq, mpos);
    k_ent_att<<<BB*NE_*HH, 256>>>(att, mpos);

    // hsW / tsW : [168,768] @ [768,768]
    {
        dim3 grid(DD/64, (BB*NE_ + 63)/64, 1);
        k_gemm<<<grid, 256>>>(p_ent_emb, DD, 0, Wh, DD, 0, p_hsW, DD, 0,
                              BB*NE_, DD, nullptr, nullptr, nullptr, 0);
        k_gemm<<<grid, 256>>>(p_ent_emb, DD, 0, Wt, DD, 0, p_tsW, DD, 0,
                              BB*NE_, DD, nullptr, nullptr, nullptr, 0);
    }

    k_pairw<<<BB*PP, 256>>>(hts);

    // rs : per-doc [512,1024] @ [1024,768]
    {
        dim3 grid(DD/64, PP/64, BB);
        k_gemm<<<grid, 256>>>(p_wnorm, LLEN, (long)PP*LLEN,
                              seq, DD, (long)LLEN*DD,
                              p_rs, DD, (long)PP*DD,
                              PP, LLEN, nullptr, nullptr, nullptr, 0);
    }

    // zs / zo : [2048,768] @ [768,768] + gathered E@W + bias, tanh
    {
        dim3 grid(DD/64, (BB*PP)/64, 1);
        k_gemm<<<grid, 256>>>(p_rs, DD, 0, Wh + (size_t)DD*DD, DD, 0, p_zs, DD, 0,
                              BB*PP, DD, bh, p_hsW, hts, 0);
        k_gemm<<<grid, 256>>>(p_rs, DD, 0, Wt + (size_t)DD*DD, DD, 0, p_zo, DD, 0,
                              BB*PP, DD, bt, p_tsW, hts, 1);
    }

    k_bilinear<<<dim3(PP/TPB2, BB, 4), 256, SMEM_BI>>>(Wbi);
    k_finish<<<(BB*PP*NL_ + 255)/256, 256>>>(out, bbi);
}

// round 7
// speedup vs baseline: 5.2330x; 1.5128x over previous
#include <cuda_runtime.h>
#include <cuda_bf16.h>
#include <cstdint>
#include <math.h>

#define BB   4
#define LLEN 1024
#define DD   768
#define HH   12
#define NE_  42
#define MM   4
#define PP   512
#define NL_  97
#define NG_  12      // D / BLK
#define NT_  13      // n-tiles of 8 (97 -> 104)

// ---------------- scratch (static device globals; no runtime allocation) ----
__device__ float g_ent_emb[BB*NE_*DD];
__device__ float g_ent_att[BB*NE_*HH*LLEN];
__device__ float g_wnorm[BB*PP*LLEN];
__device__ float g_rs[BB*PP*DD];
__device__ float g_hsW[BB*NE_*DD];
__device__ float g_tsW[BB*NE_*DD];
__device__ float g_zs[BB*PP*DD];
__device__ float g_zo[BB*PP*DD];
__device__ float g_part[NG_][BB*PP*NL_];               // bilinear partials per group
// Pre-packed B fragments for mma.m16n8k16: [g][s=0..255][t=0..12][lane]
// uint4 = {bhi0, bhi1, blo0, blo1}   (~20.4 MB)
__device__ uint4 g_Wfrag[(size_t)NG_*256*NT_*32];

// ---------------- helpers ---------------------------------------------------
__device__ __forceinline__ void cpa16(void* dst, const void* src){
    unsigned d = (unsigned)__cvta_generic_to_shared(dst);
    asm volatile("cp.async.cg.shared.global [%0], [%1], 16;\n" :: "r"(d), "l"(src));
}
__device__ __forceinline__ void cpa_commit(){ asm volatile("cp.async.commit_group;\n"); }
__device__ __forceinline__ void cpa_wait1(){ asm volatile("cp.async.wait_group 1;\n"); }
__device__ __forceinline__ void cpa_wait0(){ asm volatile("cp.async.wait_group 0;\n"); }

// bf16 two-term split, pack 2 elems per u32 (low half = first element)
__device__ __forceinline__ uint32_t pack_split(float a, float b, uint32_t& lo){
    __nv_bfloat16 ha = __float2bfloat16(a), hb = __float2bfloat16(b);
    float ra = a - __bfloat162float(ha);
    float rb = b - __bfloat162float(hb);
    __nv_bfloat16 la = __float2bfloat16(ra), lb = __float2bfloat16(rb);
    lo = (uint32_t)__bfloat16_as_ushort(la) | ((uint32_t)__bfloat16_as_ushort(lb) << 16);
    return (uint32_t)__bfloat16_as_ushort(ha) | ((uint32_t)__bfloat16_as_ushort(hb) << 16);
}

__device__ __forceinline__ void mma16816(float* d,
    uint32_t a0, uint32_t a1, uint32_t a2, uint32_t a3,
    uint32_t b0, uint32_t b1){
    asm volatile("mma.sync.aligned.m16n8k16.row.col.f32.bf16.bf16.f32 "
        "{%0,%1,%2,%3}, {%4,%5,%6,%7}, {%8,%9}, {%0,%1,%2,%3};\n"
        : "+f"(d[0]), "+f"(d[1]), "+f"(d[2]), "+f"(d[3])
        : "r"(a0), "r"(a1), "r"(a2), "r"(a3), "r"(b0), "r"(b1));
}

// ---------------- kernel 1: entity embeddings -------------------------------
__global__ void k_ent_emb(const float* __restrict__ seq, const int* __restrict__ mpos){
    int be = blockIdx.x;
    int b  = be / NE_;
    const int* mp = mpos + be*MM;
    int p0 = mp[0]+1, p1 = mp[1]+1, p2 = mp[2]+1, p3 = mp[3]+1;
    const float* s = seq + (size_t)b*LLEN*DD;
    for (int d = threadIdx.x; d < DD; d += blockDim.x){
        float v0 = s[(size_t)p0*DD+d], v1 = s[(size_t)p1*DD+d];
        float v2 = s[(size_t)p2*DD+d], v3 = s[(size_t)p3*DD+d];
        float mx = fmaxf(fmaxf(v0,v1), fmaxf(v2,v3));
        float sm = expf(v0-mx)+expf(v1-mx)+expf(v2-mx)+expf(v3-mx);
        g_ent_emb[(size_t)be*DD + d] = mx + logf(sm);
    }
}

// ---------------- kernel 2: entity attention rows ---------------------------
__global__ void k_ent_att(const float* __restrict__ att, const int* __restrict__ mpos){
    int beh = blockIdx.x;
    int h   = beh % HH;
    int be  = beh / HH;
    int b   = be / NE_;
    const int* mp = mpos + be*MM;
    int p0 = mp[0]+1, p1 = mp[1]+1, p2 = mp[2]+1, p3 = mp[3]+1;
    const float* A = att + ((size_t)(b*HH + h))*LLEN*LLEN;
    float* out = g_ent_att + ((size_t)be*HH + h)*LLEN;
    for (int l = threadIdx.x; l < LLEN; l += blockDim.x){
        float v = A[(size_t)p0*LLEN+l] + A[(size_t)p1*LLEN+l]
                + A[(size_t)p2*LLEN+l] + A[(size_t)p3*LLEN+l];
        out[l] = v * 0.25f;
    }
}

// ---------------- kernel 3: per-pair normalized context weights -------------
__global__ void k_pairw(const int* __restrict__ hts){
    int bp = blockIdx.x;
    int b  = bp >> 9;
    int hi = hts[bp*2+0], ti = hts[bp*2+1];
    __shared__ float sd[LLEN];
    __shared__ float red[8];
    const float* Ah = g_ent_att + ((size_t)(b*NE_ + hi))*HH*LLEN;
    const float* At = g_ent_att + ((size_t)(b*NE_ + ti))*HH*LLEN;
    float lsum = 0.f;
    for (int l = threadIdx.x; l < LLEN; l += blockDim.x){
        float s = 0.f;
        #pragma unroll
        for (int h = 0; h < HH; ++h) s += Ah[h*LLEN+l]*At[h*LLEN+l];
        sd[l] = s; lsum += s;
    }
    #pragma unroll
    for (int o = 16; o; o >>= 1) lsum += __shfl_xor_sync(0xFFFFFFFFu, lsum, o);
    if ((threadIdx.x & 31) == 0) red[threadIdx.x >> 5] = lsum;
    __syncthreads();
    float total = red[0]+red[1]+red[2]+red[3]+red[4]+red[5]+red[6]+red[7];
    float inv = 1.f / (total + (float)HH*1e-5f);
    float* wout = g_wnorm + (size_t)bp*LLEN;
    for (int l = threadIdx.x; l < LLEN; l += blockDim.x) wout[l] = sd[l]*inv;
}

// ---------------- fp32 GEMM, cp.async double-buffered -----------------------
__global__ void __launch_bounds__(256) k_gemm(
    const float* __restrict__ Ag, int lda, long sA,
    const float* __restrict__ Wg, int ldw, long sW,
    float* __restrict__ Cg, int ldc, long sC,
    int Mr, int K,
    const float* __restrict__ bias,
    const float* __restrict__ eW,
    const int* __restrict__ hts, int which)
{
    const float* A = Ag + (size_t)sA*blockIdx.z;
    const float* W = Wg + (size_t)sW*blockIdx.z;
    float*       C = Cg + (size_t)sC*blockIdx.z;
    __shared__ __align__(16) float As[2][64][20];
    __shared__ __align__(16) float Ws[2][16][64];
    int tid = threadIdx.x;
    int tx = tid & 15, ty = tid >> 4;
    int row0 = blockIdx.y*64, col0 = blockIdx.x*64;

    int ra = tid >> 2, ca = tid & 3;
    int rw = tid >> 4, cw = tid & 15;
    int rra = min(row0 + ra, Mr-1);

    cpa16(&As[0][ra][ca*4], A + (size_t)rra*lda + ca*4);
    cpa16(&Ws[0][rw][cw*4], W + (size_t)rw*ldw + col0 + cw*4);
    cpa_commit();

    int nk = K >> 4;
    float acc[4][4] = {};
    for (int kt = 0; kt < nk; ++kt){
        if (kt+1 < nk){
            int kb = (kt+1) & 1;
            cpa16(&As[kb][ra][ca*4], A + (size_t)rra*lda + (kt+1)*16 + ca*4);
            cpa16(&Ws[kb][rw][cw*4], W + (size_t)((kt+1)*16 + rw)*ldw + col0 + cw*4);
            cpa_commit();
            cpa_wait1();
        } else {
            cpa_wait0();
        }
        __syncthreads();
        int b = kt & 1;
        #pragma unroll
        for (int kk = 0; kk < 16; ++kk){
            float a0 = As[b][ty*4+0][kk], a1 = As[b][ty*4+1][kk];
            float a2 = As[b][ty*4+2][kk], a3 = As[b][ty*4+3][kk];
            float4 w = *(const float4*)&Ws[b][kk][tx*4];
            acc[0][0] += a0*w.x; acc[0][1] += a0*w.y; acc[0][2] += a0*w.z; acc[0][3] += a0*w.w;
            acc[1][0] += a1*w.x; acc[1][1] += a1*w.y; acc[1][2] += a1*w.z; acc[1][3] += a1*w.w;
            acc[2][0] += a2*w.x; acc[2][1] += a2*w.y; acc[2][2] += a2*w.z; acc[2][3] += a2*w.w;
            acc[3][0] += a3*w.x; acc[3][1] += a3*w.y; acc[3][2] += a3*w.z; acc[3][3] += a3*w.w;
        }
        __syncthreads();
    }
    #pragma unroll
    for (int i = 0; i < 4; ++i){
        int row = row0 + ty*4 + i;
        if (row >= Mr) continue;
        const float* ev = 0;
        if (eW){
            int bb = row / PP;
            int eidx = hts[row*2 + which];
            ev = eW + ((size_t)(bb*NE_ + eidx))*DD;
        }
        #pragma unroll
        for (int j = 0; j < 4; ++j){
            int col = col0 + tx*4 + j;
            float v = acc[i][j];
            if (ev) v = tanhf(v + ev[col] + bias[col]);
            C[(size_t)row*ldc + col] = v;
        }
    }
}

// ---------------- prep: W_bi -> per-thread mma B fragments ------------------
// block = (g, s): W rows g*4096 + s*16 .. +15, packed per (t, lane) as
// uint4 {bhi0,bhi1,blo0,blo1}; b0 covers k = q*2,q*2+1, b1 covers +8,+9,
// col n = t*8 + (lane>>2). Cols 97..103 zero.
__global__ void __launch_bounds__(128) k_prepW(const float* __restrict__ Wbi){
    int bid = blockIdx.x;
    int g = bid >> 8, s = bid & 255;
    __shared__ float w_sh[16][104];
    int tid = threadIdx.x;
    for (int idx = tid; idx < 16*104; idx += 128){
        int r = idx / 104, n = idx - r*104;
        w_sh[r][n] = (n < NL_) ? Wbi[(size_t)(g*4096 + s*16 + r)*NL_ + n] : 0.f;
    }
    __syncthreads();
    for (int e = tid; e < NT_*32; e += 128){
        int t = e >> 5, lane = e & 31;
        int gid = lane >> 2, q = lane & 3;
        int n = t*8 + gid;
        int k0 = q*2;
        float w0 = w_sh[k0][n],   w1 = w_sh[k0+1][n];
        float w2 = w_sh[k0+8][n], w3 = w_sh[k0+9][n];
        uint4 F; uint32_t l0, l1;
        F.x = pack_split(w0, w1, l0);
        F.y = pack_split(w2, w3, l1);
        F.z = l0; F.w = l1;
        g_Wfrag[(((size_t)g*256 + s)*NT_ + t)*32 + lane] = F;
    }
}

// ---------------- HMMA bf16-split grouped bilinear --------------------------
// grid (32 pair-tiles of 64, 12 groups); 256 thr = 8 warps:
// pb = wid>>1 owns pairs pb*16..+15 (m16), nh = wid&1 owns n-tiles nh*6..nh*6+6.
// K per group = 4096 = 256 k-steps of 16. A generated in regs from zs/zo SMEM.
__global__ void __launch_bounds__(256,2) k_bilinear(){
    __shared__ float zs_sh[64*65];
    __shared__ float zo_sh[64*65];
    int tid = threadIdx.x, lane = tid & 31, wid = tid >> 5;
    int pb = wid >> 1, nh = wid & 1;
    int g  = blockIdx.y;
    int p0 = blockIdx.x * 64;

    // stage zs/zo for this (pair-tile, group): [64 pairs][64 cols], pitch 65
    for (int idx = tid; idx < 64*16; idx += 256){
        int p = idx >> 4, c4 = idx & 15;
        float4 vs = *(const float4*)(g_zs + (size_t)(p0+p)*DD + g*64 + c4*4);
        float4 vo = *(const float4*)(g_zo + (size_t)(p0+p)*DD + g*64 + c4*4);
        zs_sh[p*65 + c4*4+0] = vs.x; zs_sh[p*65 + c4*4+1] = vs.y;
        zs_sh[p*65 + c4*4+2] = vs.z; zs_sh[p*65 + c4*4+3] = vs.w;
        zo_sh[p*65 + c4*4+0] = vo.x; zo_sh[p*65 + c4*4+1] = vo.y;
        zo_sh[p*65 + c4*4+2] = vo.z; zo_sh[p*65 + c4*4+3] = vo.w;
    }
    __syncthreads();

    int gid = lane >> 2, q = lane & 3;
    int r0 = pb*16 + gid, r8 = r0 + 8;
    int t0 = nh * 6;                      // tiles t0..t0+6 (t=6 overlaps: same value)
    const uint4* bbase = g_Wfrag + (((size_t)g*256)*NT_ + t0)*32 + lane;

    float acc[7][4];
    #pragma unroll
    for (int tt = 0; tt < 7; ++tt){
        acc[tt][0] = 0.f; acc[tt][1] = 0.f; acc[tt][2] = 0.f; acc[tt][3] = 0.f;
    }

    for (int s = 0; s < 256; ++s){
        uint4 Bf[7];
        const uint4* bp = bbase + (size_t)s*(NT_*32);
        #pragma unroll
        for (int tt = 0; tt < 7; ++tt) Bf[tt] = bp[tt*32];

        int i  = s >> 2;
        int c0 = ((s & 3) << 4) + q*2;
        float zr0 = zs_sh[r0*65 + i], zr8 = zs_sh[r8*65 + i];
        float o00 = zo_sh[r0*65 + c0],   o01 = zo_sh[r0*65 + c0+1];
        float o08 = zo_sh[r0*65 + c0+8], o09 = zo_sh[r0*65 + c0+9];
        float o80 = zo_sh[r8*65 + c0],   o81 = zo_sh[r8*65 + c0+1];
        float o88 = zo_sh[r8*65 + c0+8], o89 = zo_sh[r8*65 + c0+9];
        uint32_t al0, al1, al2, al3;
        uint32_t ah0 = pack_split(zr0*o00, zr0*o01, al0);
        uint32_t ah1 = pack_split(zr8*o80, zr8*o81, al1);
        uint32_t ah2 = pack_split(zr0*o08, zr0*o09, al2);
        uint32_t ah3 = pack_split(zr8*o88, zr8*o89, al3);

        #pragma unroll
        for (int tt = 0; tt < 7; ++tt){
            mma16816(acc[tt], ah0, ah1, ah2, ah3, Bf[tt].x, Bf[tt].y);  // hi*hi
            mma16816(acc[tt], ah0, ah1, ah2, ah3, Bf[tt].z, Bf[tt].w);  // hi*lo
            mma16816(acc[tt], al0, al1, al2, al3, Bf[tt].x, Bf[tt].y);  // lo*hi
        }
    }

    // epilogue: D[row gid(+8), col q*2(+1)] per tile
    int row0g = p0 + r0, row8g = p0 + r8;
    #pragma unroll
    for (int tt = 0; tt < 7; ++tt){
        int n0 = (t0 + tt)*8 + q*2;
        if (n0 < NL_){
            g_part[g][(size_t)row0g*NL_ + n0] = acc[tt][0];
            g_part[g][(size_t)row8g*NL_ + n0] = acc[tt][2];
        }
        if (n0 + 1 < NL_){
            g_part[g][(size_t)row0g*NL_ + n0+1] = acc[tt][1];
            g_part[g][(size_t)row8g*NL_ + n0+1] = acc[tt][3];
        }
    }
}

// ---------------- finish: sum 12 partials + bias ----------------------------
__global__ void k_finish(float* __restrict__ out, const float* __restrict__ b_bi){
    int i = blockIdx.x*blockDim.x + threadIdx.x;
    if (i < BB*PP*NL_){
        float s = b_bi[i % NL_];
        #pragma unroll
        for (int q = 0; q < NG_; ++q) s += g_part[q][i];
        out[i] = s;
    }
}

// ---------------- launch ----------------------------------------------------
extern "C" void kernel_launch(void* const* d_in, const int* in_sizes, int n_in,
                              void* d_out, int out_size){
    const float* seq  = (const float*)d_in[0];
    const float* att  = (const float*)d_in[1];
    const int*   mpos = (const int*)  d_in[2];
    const int*   hts  = (const int*)  d_in[3];
    const float* Wh   = (const float*)d_in[4];
    const float* bh   = (const float*)d_in[5];
    const float* Wt   = (const float*)d_in[6];
    const float* bt   = (const float*)d_in[7];
    const float* Wbi  = (const float*)d_in[8];
    const float* bbi  = (const float*)d_in[9];
    float* out = (float*)d_out;

    float *p_ent_emb, *p_wnorm, *p_rs, *p_hsW, *p_tsW, *p_zs, *p_zo;
    cudaGetSymbolAddress((void**)&p_ent_emb, g_ent_emb);
    cudaGetSymbolAddress((void**)&p_wnorm,   g_wnorm);
    cudaGetSymbolAddress((void**)&p_rs,      g_rs);
    cudaGetSymbolAddress((void**)&p_hsW,     g_hsW);
    cudaGetSymbolAddress((void**)&p_tsW,     g_tsW);
    cudaGetSymbolAddress((void**)&p_zs,      g_zs);
    cudaGetSymbolAddress((void**)&p_zo,      g_zo);

    k_prepW<<<NG_*256, 128>>>(Wbi);             // independent of data path
    k_ent_emb<<<BB*NE_, 256>>>(seq, mpos);
    k_ent_att<<<BB*NE_*HH, 256>>>(att, mpos);

    {
        dim3 grid(DD/64, (BB*NE_ + 63)/64, 1);
        k_gemm<<<grid, 256>>>(p_ent_emb, DD, 0, Wh, DD, 0, p_hsW, DD, 0,
                              BB*NE_, DD, nullptr, nullptr, nullptr, 0);
        k_gemm<<<grid, 256>>>(p_ent_emb, DD, 0, Wt, DD, 0, p_tsW, DD, 0,
                              BB*NE_, DD, nullptr, nullptr, nullptr, 0);
    }

    k_pairw<<<BB*PP, 256>>>(hts);

    {
        dim3 grid(DD/64, PP/64, BB);
        k_gemm<<<grid, 256>>>(p_wnorm, LLEN, (long)PP*LLEN,
                              seq, DD, (long)LLEN*DD,
                              p_rs, DD, (long)PP*DD,
                              PP, LLEN, nullptr, nullptr, nullptr, 0);
    }

    {
        dim3 grid(DD/64, (BB*PP)/64, 1);
        k_gemm<<<grid, 256>>>(p_rs, DD, 0, Wh + (size_t)DD*DD, DD, 0, p_zs, DD, 0,
                              BB*PP, DD, bh, p_hsW, hts, 0);
        k_gemm<<<grid, 256>>>(p_rs, DD, 0, Wt + (size_t)DD*DD, DD, 0, p_zo, DD, 0,
                              BB*PP, DD, bt, p_tsW, hts, 1);
    }

    k_bilinear<<<dim3(32, NG_), 256>>>();
    k_finish<<<(BB*PP*NL_ + 255)/256, 256>>>(out, bbi);
}